// round 6
// baseline (speedup 1.0000x reference)
#include <cuda_runtime.h>
#include <cuda_bf16.h>
#include <cstdint>

typedef unsigned long long ull;

#define NP 2809          // 53*53 patches
#define NPAD 2816        // 22*128
#define LW 53
#define NM 8192          // memories
#define KD 3072          // 3*32*32
#define XPW 84
#define XPC 7056         // 84*84
#define MARGIN 12.0f

#define BM 128
#define BN 256
#define BK 32
#define KSTEPS (KD / BK)   // 96
#define LDT 40             // smem tile leading dim (halves): conflict-free for ldmatrix
#define STAGE_BYTES ((BM + BN) * LDT * 2)   // 30720
#define NSTAGE 3
#define GEMM_SMEM (NSTAGE * STAGE_BYTES)    // 92160

// ---------------- scratch (device globals; no allocations allowed) ----------
__device__ __align__(16) float g_xp[3 * XPC];
__device__ float g_memsq[NM];
__device__ ull   g_best[NP];                    // approx (pass1) key
__device__ ull   g_bestx[NP];                   // exact (rescore) key
__device__ __align__(16) float g_D[(size_t)NP * NM];       // ~92 MB approx distances
__device__ __align__(16) float g_recon[(size_t)NP * KD];   // ~34.5 MB
__device__ __align__(16) __nv_bfloat16 g_A[(size_t)NPAD * KD];   // 17.3 MB
__device__ __align__(16) __nv_bfloat16 g_Bb[(size_t)NM * KD];    // 50 MB
__device__ unsigned int g_maxord;

// ---------------- helpers ---------------------------------------------------
__device__ __forceinline__ unsigned int ford(float f) {
    unsigned int u = __float_as_uint(f);
    return (u & 0x80000000u) ? ~u : (u | 0x80000000u);
}
__device__ __forceinline__ float fordinv(unsigned int o) {
    unsigned int u = (o & 0x80000000u) ? (o ^ 0x80000000u) : ~o;
    return __uint_as_float(u);
}
__device__ __forceinline__ ull mkkey(float d, int m) {
    return ((ull)ford(d) << 32) | (unsigned int)m;
}
__device__ __forceinline__ uint32_t s2u(const void* p) {
    uint32_t a;
    asm("{ .reg .u64 t; cvta.to.shared.u64 t, %1; cvt.u32.u64 %0, t; }" : "=r"(a) : "l"(p));
    return a;
}
__device__ __forceinline__ uint32_t packbf2(float a, float b) {
    return ((uint32_t)__bfloat16_as_ushort(__float2bfloat16(b)) << 16) |
           (uint32_t)__bfloat16_as_ushort(__float2bfloat16(a));
}
__device__ __forceinline__ void ldsm4(uint32_t* r, uint32_t addr) {
    asm volatile("ldmatrix.sync.aligned.m8n8.x4.shared.b16 {%0,%1,%2,%3}, [%4];"
                 : "=r"(r[0]), "=r"(r[1]), "=r"(r[2]), "=r"(r[3]) : "r"(addr));
}
__device__ __forceinline__ void mma16816(float* d, const uint32_t* a, const uint32_t* b) {
    asm volatile("mma.sync.aligned.m16n8k16.row.col.f32.bf16.bf16.f32 "
                 "{%0,%1,%2,%3}, {%4,%5,%6,%7}, {%8,%9}, {%0,%1,%2,%3};"
                 : "+f"(d[0]), "+f"(d[1]), "+f"(d[2]), "+f"(d[3])
                 : "r"(a[0]), "r"(a[1]), "r"(a[2]), "r"(a[3]), "r"(b[0]), "r"(b[1]));
}

// ---------------- kernel 1: build padded image + init -----------------------
__global__ void k_init(const float* __restrict__ img) {
    int idx = blockIdx.x * blockDim.x + threadIdx.x;
    if (idx < 3 * XPC) {
        int c = idx / XPC, rem = idx - c * XPC;
        int r = rem / XPW, col = rem - r * XPW;
        int h = r - 10, w = col - 10;
        float v = 0.f;
        if ((unsigned)h < 64u && (unsigned)w < 64u) v = img[(h * 64 + w) * 3 + c];
        g_xp[idx] = v;
    }
    if (idx < NP) g_best[idx] = ~0ull;
    if (idx == 0) g_maxord = 0u;
}

// ---------------- kernel 2: build bf16 A matrix (patches) -------------------
__global__ void k_buildA() {
    int e = blockIdx.x * blockDim.x + threadIdx.x;
    if (e >= NPAD * (KD / 8)) return;
    int m = e / (KD / 8), r = e - m * (KD / 8);
    int k = r * 8;
    uint32_t w0 = 0, w1 = 0, w2 = 0, w3 = 0;
    if (m < NP) {
        int i = m / LW, j = m - i * LW;
        int c = k >> 10, rem = k & 1023, kh = rem >> 5, kw = rem & 31;
        const float* src = &g_xp[c * XPC + (i + kh) * XPW + j + kw];
        w0 = packbf2(src[0], src[1]);
        w1 = packbf2(src[2], src[3]);
        w2 = packbf2(src[4], src[5]);
        w3 = packbf2(src[6], src[7]);
    }
    *(uint4*)&g_A[(size_t)m * KD + k] = make_uint4(w0, w1, w2, w3);
}

// ---------------- kernel 3: convert mem to bf16 + fused row squared norms ---
__global__ void __launch_bounds__(256) k_bconv(const float* __restrict__ mem) {
    __shared__ float red[8];
    int row = blockIdx.x, tid = threadIdx.x;
    const float4* src = (const float4*)(mem + (size_t)row * KD);
    float s = 0.f;
#pragma unroll
    for (int t = 0; t < 3; ++t) {                 // 3*256*4 = 3072
        int e = tid + t * 256;
        float4 v = src[e];
        *(uint2*)&g_Bb[(size_t)row * KD + e * 4] =
            make_uint2(packbf2(v.x, v.y), packbf2(v.z, v.w));
        s += v.x * v.x + v.y * v.y + v.z * v.z + v.w * v.w;
    }
#pragma unroll
    for (int o = 16; o; o >>= 1) s += __shfl_xor_sync(~0u, s, o);
    if ((tid & 31) == 0) red[tid >> 5] = s;
    __syncthreads();
    if (tid == 0) {
        float t = 0.f;
#pragma unroll
        for (int i = 0; i < 8; ++i) t += red[i];
        g_memsq[row] = t;
    }
}

// ---------------- kernel 4: bf16 mma.sync GEMM + approx argmin + D write ----
// CTA 128x256, BK=32, 3-stage cp.async ring. 8 warps (2M x 4N),
// warp tile 64x64 via ldmatrix + mma.m16n8k16, register-direct epilogue.
__global__ void __launch_bounds__(256, 1) k_gemm() {
    extern __shared__ __align__(16) char dynsm[];
    __shared__ float s_msq[BN];

    int tid = threadIdx.x;
    int w = tid >> 5, lane = tid & 31;
    int warp_m = w & 1, warp_n = w >> 1;
    int p0 = blockIdx.x * BM, m0 = blockIdx.y * BN;

    if (tid < BN) s_msq[tid] = g_memsq[m0 + tid];

    uint32_t smbase = s2u(dynsm);

    // conflict-free store mapping (per 8-lane phase: same chunk, rows 0..7)
    auto load_stage = [&](int st, int k0) {
        uint32_t sb = smbase + st * STAGE_BYTES;
        int rowA = tid & 127, cA0 = tid >> 7;
#pragma unroll
        for (int i = 0; i < 2; ++i) {             // A: 128 rows x 4 chunks
            int c = cA0 + 2 * i;
            uint32_t d = sb + (rowA * LDT + c * 8) * 2;
            const void* sp = &g_A[(size_t)(p0 + rowA) * KD + k0 + c * 8];
            asm volatile("cp.async.cg.shared.global [%0], [%1], 16;" :: "r"(d), "l"(sp));
        }
#pragma unroll
        for (int i = 0; i < 4; ++i) {             // B: 256 rows x 4 chunks
            uint32_t d = sb + (BM * LDT + tid * LDT + i * 8) * 2;
            const void* sp = &g_Bb[(size_t)(m0 + tid) * KD + k0 + i * 8];
            asm volatile("cp.async.cg.shared.global [%0], [%1], 16;" :: "r"(d), "l"(sp));
        }
        asm volatile("cp.async.commit_group;");
    };

    // per-thread ldmatrix intra-stage byte offsets
    uint32_t offA[4], offB[4];
#pragma unroll
    for (int fm = 0; fm < 4; ++fm)
        offA[fm] = ((warp_m * 64 + fm * 16 + (lane & 15)) * LDT + (lane >> 4) * 8) * 2;
#pragma unroll
    for (int fb = 0; fb < 4; ++fb)
        offB[fb] = (BM * LDT +
                    (warp_n * 64 + fb * 16 + (lane & 7) + ((lane >> 4) & 1) * 8) * LDT +
                    ((lane >> 3) & 1) * 8) * 2;

    float acc[4][8][4];
#pragma unroll
    for (int fm = 0; fm < 4; ++fm)
#pragma unroll
        for (int fn = 0; fn < 8; ++fn)
#pragma unroll
            for (int q = 0; q < 4; ++q) acc[fm][fn][q] = 0.f;

    load_stage(0, 0);
    load_stage(1, BK);

    for (int kt = 0; kt < KSTEPS; ++kt) {
        int cur = kt % NSTAGE;
        if (kt + 1 < KSTEPS) asm volatile("cp.async.wait_group 1;");
        else                 asm volatile("cp.async.wait_group 0;");
        __syncthreads();
        if (kt + 2 < KSTEPS) load_stage((kt + 2) % NSTAGE, (kt + 2) * BK);

        uint32_t sb = smbase + cur * STAGE_BYTES;
        uint32_t a[2][4][4], b[2][4][4];
#pragma unroll
        for (int ks = 0; ks < 2; ++ks) {
#pragma unroll
            for (int fm = 0; fm < 4; ++fm) ldsm4(a[ks][fm], sb + offA[fm] + ks * 32);
#pragma unroll
            for (int fb = 0; fb < 4; ++fb) ldsm4(b[ks][fb], sb + offB[fb] + ks * 32);
        }
#pragma unroll
        for (int ks = 0; ks < 2; ++ks)
#pragma unroll
            for (int fm = 0; fm < 4; ++fm)
#pragma unroll
                for (int fb = 0; fb < 4; ++fb) {
                    mma16816(acc[fm][fb * 2],     a[ks][fm], &b[ks][fb][0]);
                    mma16816(acc[fm][fb * 2 + 1], a[ks][fm], &b[ks][fb][2]);
                }
        __syncthreads();
    }

    // register-direct epilogue: d = memsq - 2*score
    // D frag layout: rows lane>>2 and +8; cols (lane&3)*2, +1
    int q = lane & 3, rr = lane >> 2;
#pragma unroll
    for (int fm = 0; fm < 4; ++fm) {
        int pA = p0 + warp_m * 64 + fm * 16 + rr;
        int pB = pA + 8;
        bool vA = pA < NP, vB = pB < NP;
        ull keyA = ~0ull, keyB = ~0ull;
#pragma unroll
        for (int fn = 0; fn < 8; ++fn) {
            int nloc = warp_n * 64 + fn * 8 + q * 2;
            int mcol = m0 + nloc;
            float d0 = s_msq[nloc]     - 2.f * acc[fm][fn][0];
            float d1 = s_msq[nloc + 1] - 2.f * acc[fm][fn][1];
            float d2 = s_msq[nloc]     - 2.f * acc[fm][fn][2];
            float d3 = s_msq[nloc + 1] - 2.f * acc[fm][fn][3];
            keyA = min(keyA, min(mkkey(d0, mcol), mkkey(d1, mcol + 1)));
            keyB = min(keyB, min(mkkey(d2, mcol), mkkey(d3, mcol + 1)));
            if (vA) *(float2*)&g_D[(size_t)pA * NM + mcol] = make_float2(d0, d1);
            if (vB) *(float2*)&g_D[(size_t)pB * NM + mcol] = make_float2(d2, d3);
        }
        // quad reduction (lanes 4r..4r+3 share rows pA/pB)
#pragma unroll
        for (int o = 1; o < 4; o <<= 1) {
            keyA = min(keyA, __shfl_xor_sync(~0u, keyA, o));
            keyB = min(keyB, __shfl_xor_sync(~0u, keyB, o));
        }
        if (q == 0) {
            if (vA) atomicMin(&g_best[pA], keyA);
            if (vB) atomicMin(&g_best[pB], keyB);
        }
    }
}

// ---------------- kernel 5: exact rescore of margin candidates --------------
__global__ void k_rescore(const float* __restrict__ mem) {
    __shared__ __align__(16) float s_patch[KD];
    __shared__ int s_cand[128];
    __shared__ int s_n;
    __shared__ float s_part[8];
    __shared__ ull s_bestk;

    int p = blockIdx.x;
    int tid = threadIdx.x;
    int i = p / LW, j = p - i * LW;
    for (int k = tid; k < KD; k += 256) {
        int c = k >> 10, rem = k & 1023, kh = rem >> 5, kw = rem & 31;
        s_patch[k] = g_xp[c * XPC + (i + kh) * XPW + j + kw];
    }
    if (tid == 0) { s_n = 0; s_bestk = ~0ull; }
    __syncthreads();

    float thr = fordinv((unsigned int)(g_best[p] >> 32)) + MARGIN;
    const float* Drow = &g_D[(size_t)p * NM];
    for (int m = tid; m < NM; m += 256) {
        if (Drow[m] < thr) {
            int pos = atomicAdd(&s_n, 1);
            if (pos < 128) s_cand[pos] = m;
        }
    }
    __syncthreads();
    int n = min(s_n, 128);
    for (int ci = 0; ci < n; ++ci) {
        int m = s_cand[ci];
        const float* mr = mem + (size_t)m * KD;
        float part = 0.f;
        for (int k = tid; k < KD; k += 256) part += s_patch[k] * mr[k];
#pragma unroll
        for (int o = 16; o; o >>= 1) part += __shfl_xor_sync(~0u, part, o);
        if ((tid & 31) == 0) s_part[tid >> 5] = part;
        __syncthreads();
        if (tid == 0) {
            float dot = 0.f;
#pragma unroll
            for (int w = 0; w < 8; ++w) dot += s_part[w];
            float d = g_memsq[m] - 2.f * dot;
            ull k = mkkey(d, m);
            if (k < s_bestk) s_bestk = k;
        }
        __syncthreads();
    }
    if (tid == 0) g_bestx[p] = s_bestk;
}

// ---------------- kernel 6: gather recon rows -------------------------------
__global__ void k_recon(const float* __restrict__ mem2, const int* __restrict__ mapping) {
    int p = blockIdx.x;
    int nn = (int)(g_bestx[p] & 0xFFFFFFFFull);
    int row = mapping[nn];
    const float4* src = (const float4*)(mem2 + (size_t)row * KD);
    float4* dst = (float4*)(g_recon + (size_t)p * KD);
    for (int t = threadIdx.x; t < KD / 4; t += 256) dst[t] = src[t];
}

// ---------------- kernel 7: overlap-add (gather form) + block max -----------
__global__ void k_overlap(float* __restrict__ out) {
    __shared__ __align__(16) float s[LW * 32];
    __shared__ float red[4][64];
    int bc = blockIdx.x;
    int c = bc >> 6, h = bc & 63;
    int r = h + 10;
    int tid = threadIdx.x;
    int w = tid & 63, grp = tid >> 6;
    int cc = w + 10;
    int jmin = max(0, cc - 31), jmax = min(LW - 1, cc);
    int ilo = max(0, r - 31), ihi = min(LW - 1, r);

    float sum = 0.f;
    for (int i = ilo; i <= ihi; ++i) {
        int kh = r - i;
        __syncthreads();
        for (int e = tid; e < LW * 8; e += 256) {
            int jj = e >> 3, q = e & 7;
            *(float4*)&s[jj * 32 + q * 4] =
                *(const float4*)&g_recon[(size_t)(i * LW + jj) * KD + c * 1024 + kh * 32 + q * 4];
        }
        __syncthreads();
        for (int jx = jmin + grp; jx <= jmax; jx += 4)
            sum += s[jx * 32 + (cc - jx)];
    }
    red[grp][w] = sum;
    __syncthreads();
    if (tid < 64) {
        float v = red[0][tid] + red[1][tid] + red[2][tid] + red[3][tid];
        out[(h * 64 + tid) * 3 + c] = v;
        red[0][tid] = v;
    }
    __syncthreads();
    if (tid == 0) {
        float mx = red[0][0];
        for (int t = 1; t < 64; ++t) mx = fmaxf(mx, red[0][t]);
        atomicMax(&g_maxord, ford(mx));
    }
}

// ---------------- kernel 8: normalize by global max -------------------------
__global__ void k_norm(float* __restrict__ out) {
    int idx = blockIdx.x * blockDim.x + threadIdx.x;
    if (idx < 64 * 64 * 3) out[idx] = out[idx] / fordinv(g_maxord);
}

// ---------------- launch -----------------------------------------------------
extern "C" void kernel_launch(void* const* d_in, const int* in_sizes, int n_in,
                              void* d_out, int out_size) {
    const float* img     = (const float*)d_in[0];
    const float* mem     = (const float*)d_in[1];
    const float* mem2    = (const float*)d_in[2];
    const int*   mapping = (const int*)d_in[3];
    float* out = (float*)d_out;

    cudaFuncSetAttribute(k_gemm, cudaFuncAttributeMaxDynamicSharedMemorySize, GEMM_SMEM);

    k_init<<<(3 * XPC + 255) / 256, 256>>>(img);
    k_buildA<<<(NPAD * (KD / 8) + 255) / 256, 256>>>();
    k_bconv<<<NM, 256>>>(mem);
    dim3 gg(NPAD / BM, NM / BN);
    k_gemm<<<gg, 256, GEMM_SMEM>>>();
    k_rescore<<<NP, 256>>>(mem);
    k_recon<<<NP, 256>>>(mem2, mapping);
    k_overlap<<<192, 256>>>(out);
    k_norm<<<48, 256>>>(out);
}

// round 7
// speedup vs baseline: 1.1257x; 1.1257x over previous
#include <cuda_runtime.h>
#include <cuda_bf16.h>
#include <cstdint>

typedef unsigned long long ull;

#define NP 2809          // 53*53 patches
#define NPAD 2816        // 22*128
#define LW 53
#define NM 8192          // memories
#define KD 3072          // 3*32*32
#define XPW 84
#define XPC 7056         // 84*84
#define MARGIN 48.0f

#define BM 128
#define BN 256
#define BK 64              // fp8 elements per K-chunk (64 bytes/row)
#define KSTEPS (KD / BK)   // 48
#define LDTB 80            // smem row stride in BYTES (64 + 16 pad, conflict-free)
#define STAGE_BYTES ((BM + BN) * LDTB)      // 30720
#define NSTAGE 3
#define GEMM_SMEM (NSTAGE * STAGE_BYTES)    // 92160

// ---------------- scratch (device globals; no allocations allowed) ----------
__device__ __align__(16) float g_xp[3 * XPC];
__device__ float g_memsq[NM];
__device__ ull   g_best[NP];                    // approx (pass1) key
__device__ ull   g_bestx[NP];                   // exact (rescore) key
__device__ __align__(16) float g_D[(size_t)NP * NM];       // ~92 MB approx distances
__device__ __align__(16) float g_recon[(size_t)NP * KD];   // ~34.5 MB
__device__ __align__(16) uint8_t g_A8[(size_t)NPAD * KD];  // 8.7 MB  e4m3 patches
__device__ __align__(16) uint8_t g_B8[(size_t)NM * KD];    // 25 MB   e4m3 memories
__device__ unsigned int g_maxord;

// ---------------- helpers ---------------------------------------------------
__device__ __forceinline__ unsigned int ford(float f) {
    unsigned int u = __float_as_uint(f);
    return (u & 0x80000000u) ? ~u : (u | 0x80000000u);
}
__device__ __forceinline__ float fordinv(unsigned int o) {
    unsigned int u = (o & 0x80000000u) ? (o ^ 0x80000000u) : ~o;
    return __uint_as_float(u);
}
__device__ __forceinline__ ull mkkey(float d, int m) {
    return ((ull)ford(d) << 32) | (unsigned int)m;
}
__device__ __forceinline__ uint32_t s2u(const void* p) {
    uint32_t a;
    asm("{ .reg .u64 t; cvta.to.shared.u64 t, %1; cvt.u32.u64 %0, t; }" : "=r"(a) : "l"(p));
    return a;
}
__device__ __forceinline__ uint32_t pack4_e4m3(float x0, float x1, float x2, float x3) {
    unsigned short lo, hi;
    asm("cvt.rn.satfinite.e4m3x2.f32 %0, %1, %2;" : "=h"(lo) : "f"(x1), "f"(x0));
    asm("cvt.rn.satfinite.e4m3x2.f32 %0, %1, %2;" : "=h"(hi) : "f"(x3), "f"(x2));
    return ((uint32_t)hi << 16) | (uint32_t)lo;
}
__device__ __forceinline__ void ldsm4(uint32_t* r, uint32_t addr) {
    asm volatile("ldmatrix.sync.aligned.m8n8.x4.shared.b16 {%0,%1,%2,%3}, [%4];"
                 : "=r"(r[0]), "=r"(r[1]), "=r"(r[2]), "=r"(r[3]) : "r"(addr));
}
__device__ __forceinline__ void mma16832(float* d, const uint32_t* a, const uint32_t* b) {
    asm volatile("mma.sync.aligned.m16n8k32.row.col.f32.e4m3.e4m3.f32 "
                 "{%0,%1,%2,%3}, {%4,%5,%6,%7}, {%8,%9}, {%0,%1,%2,%3};"
                 : "+f"(d[0]), "+f"(d[1]), "+f"(d[2]), "+f"(d[3])
                 : "r"(a[0]), "r"(a[1]), "r"(a[2]), "r"(a[3]), "r"(b[0]), "r"(b[1]));
}

// ---------------- kernel 1: build padded image + init -----------------------
__global__ void k_init(const float* __restrict__ img) {
    int idx = blockIdx.x * blockDim.x + threadIdx.x;
    if (idx < 3 * XPC) {
        int c = idx / XPC, rem = idx - c * XPC;
        int r = rem / XPW, col = rem - r * XPW;
        int h = r - 10, w = col - 10;
        float v = 0.f;
        if ((unsigned)h < 64u && (unsigned)w < 64u) v = img[(h * 64 + w) * 3 + c];
        g_xp[idx] = v;
    }
    if (idx < NP) g_best[idx] = ~0ull;
    if (idx == 0) g_maxord = 0u;
}

// ---------------- kernel 2: build e4m3 A matrix (patches) -------------------
__global__ void k_buildA() {
    int e = blockIdx.x * blockDim.x + threadIdx.x;   // NPAD * (KD/16)
    if (e >= NPAD * (KD / 16)) return;
    int m = e / (KD / 16), r = e - m * (KD / 16);
    int k = r * 16;
    uint32_t w0 = 0, w1 = 0, w2 = 0, w3 = 0;
    if (m < NP) {
        int i = m / LW, j = m - i * LW;
        int c = k >> 10, rem = k & 1023, kh = rem >> 5, kw = rem & 31;
        const float* src = &g_xp[c * XPC + (i + kh) * XPW + j + kw];
        w0 = pack4_e4m3(src[0],  src[1],  src[2],  src[3]);
        w1 = pack4_e4m3(src[4],  src[5],  src[6],  src[7]);
        w2 = pack4_e4m3(src[8],  src[9],  src[10], src[11]);
        w3 = pack4_e4m3(src[12], src[13], src[14], src[15]);
    }
    *(uint4*)&g_A8[(size_t)m * KD + k] = make_uint4(w0, w1, w2, w3);
}

// ---------------- kernel 3: convert mem to e4m3 + fused row squared norms ---
__global__ void __launch_bounds__(256) k_bconv(const float* __restrict__ mem) {
    __shared__ float red[8];
    int row = blockIdx.x, tid = threadIdx.x;
    const float4* src = (const float4*)(mem + (size_t)row * KD);
    float s = 0.f;
#pragma unroll
    for (int t = 0; t < 3; ++t) {                 // 3*256*4 = 3072
        int e = tid + t * 256;
        float4 v = src[e];
        *(uint32_t*)&g_B8[(size_t)row * KD + e * 4] = pack4_e4m3(v.x, v.y, v.z, v.w);
        s += v.x * v.x + v.y * v.y + v.z * v.z + v.w * v.w;
    }
#pragma unroll
    for (int o = 16; o; o >>= 1) s += __shfl_xor_sync(~0u, s, o);
    if ((tid & 31) == 0) red[tid >> 5] = s;
    __syncthreads();
    if (tid == 0) {
        float t = 0.f;
#pragma unroll
        for (int i = 0; i < 8; ++i) t += red[i];
        g_memsq[row] = t;
    }
}

// ---------------- kernel 4: e4m3 mma.sync GEMM + approx argmin + D write ----
// CTA 128x256, BK=64 fp8, 3-stage cp.async ring. 8 warps (2M x 4N),
// warp tile 64x64 via ldmatrix + mma.m16n8k32, register-direct epilogue.
__global__ void __launch_bounds__(256, 1) k_gemm() {
    extern __shared__ __align__(16) char dynsm[];
    __shared__ float s_msq[BN];

    int tid = threadIdx.x;
    int w = tid >> 5, lane = tid & 31;
    int warp_m = w & 1, warp_n = w >> 1;
    int p0 = blockIdx.x * BM, m0 = blockIdx.y * BN;

    if (tid < BN) s_msq[tid] = g_memsq[m0 + tid];

    uint32_t smbase = s2u(dynsm);

    auto load_stage = [&](int st, int k0) {
        uint32_t sb = smbase + st * STAGE_BYTES;
        int rowA = tid & 127, cA0 = tid >> 7;
#pragma unroll
        for (int i = 0; i < 2; ++i) {             // A: 128 rows x 4 x 16B
            int c = cA0 + 2 * i;
            uint32_t d = sb + rowA * LDTB + c * 16;
            const void* sp = &g_A8[(size_t)(p0 + rowA) * KD + k0 + c * 16];
            asm volatile("cp.async.cg.shared.global [%0], [%1], 16;" :: "r"(d), "l"(sp));
        }
#pragma unroll
        for (int i = 0; i < 4; ++i) {             // B: 256 rows x 4 x 16B
            uint32_t d = sb + BM * LDTB + tid * LDTB + i * 16;
            const void* sp = &g_B8[(size_t)(m0 + tid) * KD + k0 + i * 16];
            asm volatile("cp.async.cg.shared.global [%0], [%1], 16;" :: "r"(d), "l"(sp));
        }
        asm volatile("cp.async.commit_group;");
    };

    // ldmatrix byte offsets (16B segment = 16 fp8 k-values)
    uint32_t offA[4], offB[4];
#pragma unroll
    for (int fm = 0; fm < 4; ++fm)
        offA[fm] = (warp_m * 64 + fm * 16 + (lane & 15)) * LDTB + (lane >> 4) * 16;
#pragma unroll
    for (int fb = 0; fb < 4; ++fb)
        offB[fb] = BM * LDTB +
                   (warp_n * 64 + fb * 16 + (lane & 7) + ((lane >> 4) & 1) * 8) * LDTB +
                   ((lane >> 3) & 1) * 16;

    float acc[4][8][4];
#pragma unroll
    for (int fm = 0; fm < 4; ++fm)
#pragma unroll
        for (int fn = 0; fn < 8; ++fn)
#pragma unroll
            for (int q = 0; q < 4; ++q) acc[fm][fn][q] = 0.f;

    load_stage(0, 0);
    load_stage(1, BK);

    for (int kt = 0; kt < KSTEPS; ++kt) {
        int cur = kt % NSTAGE;
        if (kt + 1 < KSTEPS) asm volatile("cp.async.wait_group 1;");
        else                 asm volatile("cp.async.wait_group 0;");
        __syncthreads();
        if (kt + 2 < KSTEPS) load_stage((kt + 2) % NSTAGE, (kt + 2) * BK);

        uint32_t sb = smbase + cur * STAGE_BYTES;
        uint32_t a[2][4][4], b[2][4][4];
#pragma unroll
        for (int ks = 0; ks < 2; ++ks) {          // two k32 halves of 64B row
#pragma unroll
            for (int fm = 0; fm < 4; ++fm) ldsm4(a[ks][fm], sb + offA[fm] + ks * 32);
#pragma unroll
            for (int fb = 0; fb < 4; ++fb) ldsm4(b[ks][fb], sb + offB[fb] + ks * 32);
        }
#pragma unroll
        for (int ks = 0; ks < 2; ++ks)
#pragma unroll
            for (int fm = 0; fm < 4; ++fm)
#pragma unroll
                for (int fb = 0; fb < 4; ++fb) {
                    mma16832(acc[fm][fb * 2],     a[ks][fm], &b[ks][fb][0]);
                    mma16832(acc[fm][fb * 2 + 1], a[ks][fm], &b[ks][fb][2]);
                }
        __syncthreads();
    }

    // register-direct epilogue: d = memsq - 2*score
    int q = lane & 3, rr = lane >> 2;
#pragma unroll
    for (int fm = 0; fm < 4; ++fm) {
        int pA = p0 + warp_m * 64 + fm * 16 + rr;
        int pB = pA + 8;
        bool vA = pA < NP, vB = pB < NP;
        ull keyA = ~0ull, keyB = ~0ull;
#pragma unroll
        for (int fn = 0; fn < 8; ++fn) {
            int nloc = warp_n * 64 + fn * 8 + q * 2;
            int mcol = m0 + nloc;
            float d0 = s_msq[nloc]     - 2.f * acc[fm][fn][0];
            float d1 = s_msq[nloc + 1] - 2.f * acc[fm][fn][1];
            float d2 = s_msq[nloc]     - 2.f * acc[fm][fn][2];
            float d3 = s_msq[nloc + 1] - 2.f * acc[fm][fn][3];
            keyA = min(keyA, min(mkkey(d0, mcol), mkkey(d1, mcol + 1)));
            keyB = min(keyB, min(mkkey(d2, mcol), mkkey(d3, mcol + 1)));
            if (vA) *(float2*)&g_D[(size_t)pA * NM + mcol] = make_float2(d0, d1);
            if (vB) *(float2*)&g_D[(size_t)pB * NM + mcol] = make_float2(d2, d3);
        }
#pragma unroll
        for (int o = 1; o < 4; o <<= 1) {
            keyA = min(keyA, __shfl_xor_sync(~0u, keyA, o));
            keyB = min(keyB, __shfl_xor_sync(~0u, keyB, o));
        }
        if (q == 0) {
            if (vA) atomicMin(&g_best[pA], keyA);
            if (vB) atomicMin(&g_best[pB], keyB);
        }
    }
}

// ---------------- kernel 5: exact rescore of margin candidates --------------
__global__ void k_rescore(const float* __restrict__ mem) {
    __shared__ __align__(16) float s_patch[KD];
    __shared__ int s_cand[128];
    __shared__ int s_n;
    __shared__ float s_part[8];
    __shared__ ull s_bestk;

    int p = blockIdx.x;
    int tid = threadIdx.x;
    int i = p / LW, j = p - i * LW;
    for (int k = tid; k < KD; k += 256) {
        int c = k >> 10, rem = k & 1023, kh = rem >> 5, kw = rem & 31;
        s_patch[k] = g_xp[c * XPC + (i + kh) * XPW + j + kw];
    }
    if (tid == 0) { s_n = 0; s_bestk = ~0ull; }
    __syncthreads();

    float thr = fordinv((unsigned int)(g_best[p] >> 32)) + MARGIN;
    const float* Drow = &g_D[(size_t)p * NM];
    for (int m = tid; m < NM; m += 256) {
        if (Drow[m] < thr) {
            int pos = atomicAdd(&s_n, 1);
            if (pos < 128) s_cand[pos] = m;
        }
    }
    __syncthreads();
    int n = min(s_n, 128);
    for (int ci = 0; ci < n; ++ci) {
        int m = s_cand[ci];
        const float* mr = mem + (size_t)m * KD;
        float part = 0.f;
        for (int k = tid; k < KD; k += 256) part += s_patch[k] * mr[k];
#pragma unroll
        for (int o = 16; o; o >>= 1) part += __shfl_xor_sync(~0u, part, o);
        if ((tid & 31) == 0) s_part[tid >> 5] = part;
        __syncthreads();
        if (tid == 0) {
            float dot = 0.f;
#pragma unroll
            for (int w = 0; w < 8; ++w) dot += s_part[w];
            float d = g_memsq[m] - 2.f * dot;
            ull k = mkkey(d, m);
            if (k < s_bestk) s_bestk = k;
        }
        __syncthreads();
    }
    if (tid == 0) g_bestx[p] = s_bestk;
}

// ---------------- kernel 6: gather recon rows -------------------------------
__global__ void k_recon(const float* __restrict__ mem2, const int* __restrict__ mapping) {
    int p = blockIdx.x;
    int nn = (int)(g_bestx[p] & 0xFFFFFFFFull);
    int row = mapping[nn];
    const float4* src = (const float4*)(mem2 + (size_t)row * KD);
    float4* dst = (float4*)(g_recon + (size_t)p * KD);
    for (int t = threadIdx.x; t < KD / 4; t += 256) dst[t] = src[t];
}

// ---------------- kernel 7: overlap-add (gather form) + block max -----------
__global__ void k_overlap(float* __restrict__ out) {
    __shared__ __align__(16) float s[LW * 32];
    __shared__ float red[4][64];
    int bc = blockIdx.x;
    int c = bc >> 6, h = bc & 63;
    int r = h + 10;
    int tid = threadIdx.x;
    int w = tid & 63, grp = tid >> 6;
    int cc = w + 10;
    int jmin = max(0, cc - 31), jmax = min(LW - 1, cc);
    int ilo = max(0, r - 31), ihi = min(LW - 1, r);

    float sum = 0.f;
    for (int i = ilo; i <= ihi; ++i) {
        int kh = r - i;
        __syncthreads();
        for (int e = tid; e < LW * 8; e += 256) {
            int jj = e >> 3, q = e & 7;
            *(float4*)&s[jj * 32 + q * 4] =
                *(const float4*)&g_recon[(size_t)(i * LW + jj) * KD + c * 1024 + kh * 32 + q * 4];
        }
        __syncthreads();
        for (int jx = jmin + grp; jx <= jmax; jx += 4)
            sum += s[jx * 32 + (cc - jx)];
    }
    red[grp][w] = sum;
    __syncthreads();
    if (tid < 64) {
        float v = red[0][tid] + red[1][tid] + red[2][tid] + red[3][tid];
        out[(h * 64 + tid) * 3 + c] = v;
        red[0][tid] = v;
    }
    __syncthreads();
    if (tid == 0) {
        float mx = red[0][0];
        for (int t = 1; t < 64; ++t) mx = fmaxf(mx, red[0][t]);
        atomicMax(&g_maxord, ford(mx));
    }
}

// ---------------- kernel 8: normalize by global max -------------------------
__global__ void k_norm(float* __restrict__ out) {
    int idx = blockIdx.x * blockDim.x + threadIdx.x;
    if (idx < 64 * 64 * 3) out[idx] = out[idx] / fordinv(g_maxord);
}

// ---------------- launch -----------------------------------------------------
extern "C" void kernel_launch(void* const* d_in, const int* in_sizes, int n_in,
                              void* d_out, int out_size) {
    const float* img     = (const float*)d_in[0];
    const float* mem     = (const float*)d_in[1];
    const float* mem2    = (const float*)d_in[2];
    const int*   mapping = (const int*)d_in[3];
    float* out = (float*)d_out;

    cudaFuncSetAttribute(k_gemm, cudaFuncAttributeMaxDynamicSharedMemorySize, GEMM_SMEM);

    k_init<<<(3 * XPC + 255) / 256, 256>>>(img);
    k_buildA<<<(NPAD * (KD / 16) + 255) / 256, 256>>>();
    k_bconv<<<NM, 256>>>(mem);
    dim3 gg(NPAD / BM, NM / BN);
    k_gemm<<<gg, 256, GEMM_SMEM>>>();
    k_rescore<<<NP, 256>>>(mem);
    k_recon<<<NP, 256>>>(mem2, mapping);
    k_overlap<<<192, 256>>>(out);
    k_norm<<<48, 256>>>(out);
}

// round 8
// speedup vs baseline: 1.1722x; 1.0413x over previous
#include <cuda_runtime.h>
#include <cuda_bf16.h>
#include <cstdint>

typedef unsigned long long ull;

#define NP 2809          // 53*53 patches
#define NPAD 2816        // 22*128
#define LW 53
#define NM 8192          // memories
#define KD 3072          // 3*32*32
#define XPW 84
#define XPC 7056         // 84*84
#define MARGIN 48.0f

#define BM 128
#define BN 128
#define BK 64              // fp8 elements per K-chunk (64 bytes/row)
#define KSTEPS (KD / BK)   // 48
#define LDTB 80            // smem row stride in BYTES (64 + 16 pad, conflict-free)
#define STAGE_BYTES ((BM + BN) * LDTB)      // 20480
#define NSTAGE 3
#define GEMM_SMEM (NSTAGE * STAGE_BYTES)    // 61440

// ---------------- scratch (device globals; no allocations allowed) ----------
__device__ __align__(16) float g_xp[3 * XPC];
__device__ float g_memsq[NM];
__device__ ull   g_best[NP];                    // approx (pass1) key
__device__ ull   g_bestx[NP];                   // exact (rescore) key
__device__ __align__(16) float g_D[(size_t)NP * NM];       // ~92 MB approx distances
__device__ __align__(16) float g_recon[(size_t)NP * KD];   // ~34.5 MB
__device__ __align__(16) uint8_t g_A8[(size_t)NPAD * KD];  // 8.7 MB  e4m3 patches
__device__ __align__(16) uint8_t g_B8[(size_t)NM * KD];    // 25 MB   e4m3 memories
__device__ unsigned int g_maxord;

// ---------------- helpers ---------------------------------------------------
__device__ __forceinline__ unsigned int ford(float f) {
    unsigned int u = __float_as_uint(f);
    return (u & 0x80000000u) ? ~u : (u | 0x80000000u);
}
__device__ __forceinline__ float fordinv(unsigned int o) {
    unsigned int u = (o & 0x80000000u) ? (o ^ 0x80000000u) : ~o;
    return __uint_as_float(u);
}
__device__ __forceinline__ ull mkkey(float d, int m) {
    return ((ull)ford(d) << 32) | (unsigned int)m;
}
__device__ __forceinline__ uint32_t s2u(const void* p) {
    uint32_t a;
    asm("{ .reg .u64 t; cvta.to.shared.u64 t, %1; cvt.u32.u64 %0, t; }" : "=r"(a) : "l"(p));
    return a;
}
__device__ __forceinline__ uint32_t pack4_e4m3(float x0, float x1, float x2, float x3) {
    unsigned short lo, hi;
    asm("cvt.rn.satfinite.e4m3x2.f32 %0, %1, %2;" : "=h"(lo) : "f"(x1), "f"(x0));
    asm("cvt.rn.satfinite.e4m3x2.f32 %0, %1, %2;" : "=h"(hi) : "f"(x3), "f"(x2));
    return ((uint32_t)hi << 16) | (uint32_t)lo;
}
__device__ __forceinline__ void ldsm4(uint32_t* r, uint32_t addr) {
    asm volatile("ldmatrix.sync.aligned.m8n8.x4.shared.b16 {%0,%1,%2,%3}, [%4];"
                 : "=r"(r[0]), "=r"(r[1]), "=r"(r[2]), "=r"(r[3]) : "r"(addr));
}
__device__ __forceinline__ void mma16832(float* d, const uint32_t* a, const uint32_t* b) {
    asm volatile("mma.sync.aligned.m16n8k32.row.col.f32.e4m3.e4m3.f32 "
                 "{%0,%1,%2,%3}, {%4,%5,%6,%7}, {%8,%9}, {%0,%1,%2,%3};"
                 : "+f"(d[0]), "+f"(d[1]), "+f"(d[2]), "+f"(d[3])
                 : "r"(a[0]), "r"(a[1]), "r"(a[2]), "r"(a[3]), "r"(b[0]), "r"(b[1]));
}

// ---------------- kernel 1: build padded image + init -----------------------
__global__ void k_init(const float* __restrict__ img) {
    int idx = blockIdx.x * blockDim.x + threadIdx.x;
    if (idx < 3 * XPC) {
        int c = idx / XPC, rem = idx - c * XPC;
        int r = rem / XPW, col = rem - r * XPW;
        int h = r - 10, w = col - 10;
        float v = 0.f;
        if ((unsigned)h < 64u && (unsigned)w < 64u) v = img[(h * 64 + w) * 3 + c];
        g_xp[idx] = v;
    }
    if (idx < NP) g_best[idx] = ~0ull;
    if (idx == 0) g_maxord = 0u;
}

// ---------------- kernel 2: build e4m3 A matrix (patches) -------------------
__global__ void k_buildA() {
    int e = blockIdx.x * blockDim.x + threadIdx.x;   // NPAD * (KD/16)
    if (e >= NPAD * (KD / 16)) return;
    int m = e / (KD / 16), r = e - m * (KD / 16);
    int k = r * 16;
    uint32_t w0 = 0, w1 = 0, w2 = 0, w3 = 0;
    if (m < NP) {
        int i = m / LW, j = m - i * LW;
        int c = k >> 10, rem = k & 1023, kh = rem >> 5, kw = rem & 31;
        const float* src = &g_xp[c * XPC + (i + kh) * XPW + j + kw];
        w0 = pack4_e4m3(src[0],  src[1],  src[2],  src[3]);
        w1 = pack4_e4m3(src[4],  src[5],  src[6],  src[7]);
        w2 = pack4_e4m3(src[8],  src[9],  src[10], src[11]);
        w3 = pack4_e4m3(src[12], src[13], src[14], src[15]);
    }
    *(uint4*)&g_A8[(size_t)m * KD + k] = make_uint4(w0, w1, w2, w3);
}

// ---------------- kernel 3: convert mem to e4m3 + fused row squared norms ---
__global__ void __launch_bounds__(256) k_bconv(const float* __restrict__ mem) {
    __shared__ float red[8];
    int row = blockIdx.x, tid = threadIdx.x;
    const float4* src = (const float4*)(mem + (size_t)row * KD);
    float s = 0.f;
#pragma unroll
    for (int t = 0; t < 3; ++t) {                 // 3*256*4 = 3072
        int e = tid + t * 256;
        float4 v = src[e];
        *(uint32_t*)&g_B8[(size_t)row * KD + e * 4] = pack4_e4m3(v.x, v.y, v.z, v.w);
        s += v.x * v.x + v.y * v.y + v.z * v.z + v.w * v.w;
    }
#pragma unroll
    for (int o = 16; o; o >>= 1) s += __shfl_xor_sync(~0u, s, o);
    if ((tid & 31) == 0) red[tid >> 5] = s;
    __syncthreads();
    if (tid == 0) {
        float t = 0.f;
#pragma unroll
        for (int i = 0; i < 8; ++i) t += red[i];
        g_memsq[row] = t;
    }
}

// ---------------- kernel 4: e4m3 mma.sync GEMM + approx argmin + D write ----
// CTA 128x128, BK=64 fp8, 3-stage cp.async ring, 2 CTAs/SM for overlap.
// 8 warps (2M x 4N), warp tile 64x32 via ldmatrix + mma.m16n8k32.
__global__ void __launch_bounds__(256, 2) k_gemm() {
    extern __shared__ __align__(16) char dynsm[];
    __shared__ float s_msq[BN];

    int tid = threadIdx.x;
    int w = tid >> 5, lane = tid & 31;
    int warp_m = w & 1, warp_n = w >> 1;
    int p0 = blockIdx.x * BM, m0 = blockIdx.y * BN;

    if (tid < BN) s_msq[tid] = g_memsq[m0 + tid];

    uint32_t smbase = s2u(dynsm);

    auto load_stage = [&](int st, int k0) {
        uint32_t sb = smbase + st * STAGE_BYTES;
        int row = tid & 127, c0 = tid >> 7;
#pragma unroll
        for (int i = 0; i < 2; ++i) {             // A + B: 128 rows x 4 x 16B each
            int c = c0 + 2 * i;
            uint32_t dA = sb + row * LDTB + c * 16;
            const void* spA = &g_A8[(size_t)(p0 + row) * KD + k0 + c * 16];
            asm volatile("cp.async.cg.shared.global [%0], [%1], 16;" :: "r"(dA), "l"(spA));
            uint32_t dB = sb + BM * LDTB + row * LDTB + c * 16;
            const void* spB = &g_B8[(size_t)(m0 + row) * KD + k0 + c * 16];
            asm volatile("cp.async.cg.shared.global [%0], [%1], 16;" :: "r"(dB), "l"(spB));
        }
        asm volatile("cp.async.commit_group;");
    };

    // ldmatrix byte offsets (16B segment = 16 fp8 k-values)
    uint32_t offA[4], offB[2];
#pragma unroll
    for (int fm = 0; fm < 4; ++fm)
        offA[fm] = (warp_m * 64 + fm * 16 + (lane & 15)) * LDTB + (lane >> 4) * 16;
#pragma unroll
    for (int fb = 0; fb < 2; ++fb)
        offB[fb] = BM * LDTB +
                   (warp_n * 32 + fb * 16 + (lane & 7) + ((lane >> 4) & 1) * 8) * LDTB +
                   ((lane >> 3) & 1) * 16;

    float acc[4][4][4];
#pragma unroll
    for (int fm = 0; fm < 4; ++fm)
#pragma unroll
        for (int fn = 0; fn < 4; ++fn)
#pragma unroll
            for (int q = 0; q < 4; ++q) acc[fm][fn][q] = 0.f;

    load_stage(0, 0);
    load_stage(1, BK);

    for (int kt = 0; kt < KSTEPS; ++kt) {
        int cur = kt % NSTAGE;
        if (kt + 1 < KSTEPS) asm volatile("cp.async.wait_group 1;");
        else                 asm volatile("cp.async.wait_group 0;");
        __syncthreads();
        if (kt + 2 < KSTEPS) load_stage((kt + 2) % NSTAGE, (kt + 2) * BK);

        uint32_t sb = smbase + cur * STAGE_BYTES;
#pragma unroll
        for (int ks = 0; ks < 2; ++ks) {          // two k32 halves of 64B row
            uint32_t a[4][4], b[2][4];
#pragma unroll
            for (int fm = 0; fm < 4; ++fm) ldsm4(a[fm], sb + offA[fm] + ks * 32);
#pragma unroll
            for (int fb = 0; fb < 2; ++fb) ldsm4(b[fb], sb + offB[fb] + ks * 32);
#pragma unroll
            for (int fm = 0; fm < 4; ++fm)
#pragma unroll
                for (int fb = 0; fb < 2; ++fb) {
                    mma16832(acc[fm][fb * 2],     a[fm], &b[fb][0]);
                    mma16832(acc[fm][fb * 2 + 1], a[fm], &b[fb][2]);
                }
        }
        __syncthreads();
    }

    // register-direct epilogue: d = memsq - 2*score
    int q = lane & 3, rr = lane >> 2;
#pragma unroll
    for (int fm = 0; fm < 4; ++fm) {
        int pA = p0 + warp_m * 64 + fm * 16 + rr;
        int pB = pA + 8;
        bool vA = pA < NP, vB = pB < NP;
        ull keyA = ~0ull, keyB = ~0ull;
#pragma unroll
        for (int fn = 0; fn < 4; ++fn) {
            int nloc = warp_n * 32 + fn * 8 + q * 2;
            int mcol = m0 + nloc;
            float d0 = s_msq[nloc]     - 2.f * acc[fm][fn][0];
            float d1 = s_msq[nloc + 1] - 2.f * acc[fm][fn][1];
            float d2 = s_msq[nloc]     - 2.f * acc[fm][fn][2];
            float d3 = s_msq[nloc + 1] - 2.f * acc[fm][fn][3];
            keyA = min(keyA, min(mkkey(d0, mcol), mkkey(d1, mcol + 1)));
            keyB = min(keyB, min(mkkey(d2, mcol), mkkey(d3, mcol + 1)));
            if (vA) *(float2*)&g_D[(size_t)pA * NM + mcol] = make_float2(d0, d1);
            if (vB) *(float2*)&g_D[(size_t)pB * NM + mcol] = make_float2(d2, d3);
        }
#pragma unroll
        for (int o = 1; o < 4; o <<= 1) {
            keyA = min(keyA, __shfl_xor_sync(~0u, keyA, o));
            keyB = min(keyB, __shfl_xor_sync(~0u, keyB, o));
        }
        if (q == 0) {
            if (vA) atomicMin(&g_best[pA], keyA);
            if (vB) atomicMin(&g_best[pB], keyB);
        }
    }
}

// ---------------- kernel 5: exact rescore of margin candidates --------------
__global__ void k_rescore(const float* __restrict__ mem) {
    __shared__ __align__(16) float s_patch[KD];
    __shared__ int s_cand[128];
    __shared__ int s_n;
    __shared__ float s_part[8];
    __shared__ ull s_bestk;

    int p = blockIdx.x;
    int tid = threadIdx.x;
    int i = p / LW, j = p - i * LW;
    for (int k = tid; k < KD; k += 256) {
        int c = k >> 10, rem = k & 1023, kh = rem >> 5, kw = rem & 31;
        s_patch[k] = g_xp[c * XPC + (i + kh) * XPW + j + kw];
    }
    if (tid == 0) { s_n = 0; s_bestk = ~0ull; }
    __syncthreads();

    float thr = fordinv((unsigned int)(g_best[p] >> 32)) + MARGIN;
    const float* Drow = &g_D[(size_t)p * NM];
    for (int m = tid; m < NM; m += 256) {
        if (Drow[m] < thr) {
            int pos = atomicAdd(&s_n, 1);
            if (pos < 128) s_cand[pos] = m;
        }
    }
    __syncthreads();
    int n = min(s_n, 128);
    for (int ci = 0; ci < n; ++ci) {
        int m = s_cand[ci];
        const float* mr = mem + (size_t)m * KD;
        float part = 0.f;
        for (int k = tid; k < KD; k += 256) part += s_patch[k] * mr[k];
#pragma unroll
        for (int o = 16; o; o >>= 1) part += __shfl_xor_sync(~0u, part, o);
        if ((tid & 31) == 0) s_part[tid >> 5] = part;
        __syncthreads();
        if (tid == 0) {
            float dot = 0.f;
#pragma unroll
            for (int w = 0; w < 8; ++w) dot += s_part[w];
            float d = g_memsq[m] - 2.f * dot;
            ull k = mkkey(d, m);
            if (k < s_bestk) s_bestk = k;
        }
        __syncthreads();
    }
    if (tid == 0) g_bestx[p] = s_bestk;
}

// ---------------- kernel 6: gather recon rows -------------------------------
__global__ void k_recon(const float* __restrict__ mem2, const int* __restrict__ mapping) {
    int p = blockIdx.x;
    int nn = (int)(g_bestx[p] & 0xFFFFFFFFull);
    int row = mapping[nn];
    const float4* src = (const float4*)(mem2 + (size_t)row * KD);
    float4* dst = (float4*)(g_recon + (size_t)p * KD);
    for (int t = threadIdx.x; t < KD / 4; t += 256) dst[t] = src[t];
}

// ---------------- kernel 7: overlap-add (gather form) + block max -----------
__global__ void k_overlap(float* __restrict__ out) {
    __shared__ __align__(16) float s[LW * 32];
    __shared__ float red[4][64];
    int bc = blockIdx.x;
    int c = bc >> 6, h = bc & 63;
    int r = h + 10;
    int tid = threadIdx.x;
    int w = tid & 63, grp = tid >> 6;
    int cc = w + 10;
    int jmin = max(0, cc - 31), jmax = min(LW - 1, cc);
    int ilo = max(0, r - 31), ihi = min(LW - 1, r);

    float sum = 0.f;
    for (int i = ilo; i <= ihi; ++i) {
        int kh = r - i;
        __syncthreads();
        for (int e = tid; e < LW * 8; e += 256) {
            int jj = e >> 3, q = e & 7;
            *(float4*)&s[jj * 32 + q * 4] =
                *(const float4*)&g_recon[(size_t)(i * LW + jj) * KD + c * 1024 + kh * 32 + q * 4];
        }
        __syncthreads();
        for (int jx = jmin + grp; jx <= jmax; jx += 4)
            sum += s[jx * 32 + (cc - jx)];
    }
    red[grp][w] = sum;
    __syncthreads();
    if (tid < 64) {
        float v = red[0][tid] + red[1][tid] + red[2][tid] + red[3][tid];
        out[(h * 64 + tid) * 3 + c] = v;
        red[0][tid] = v;
    }
    __syncthreads();
    if (tid == 0) {
        float mx = red[0][0];
        for (int t = 1; t < 64; ++t) mx = fmaxf(mx, red[0][t]);
        atomicMax(&g_maxord, ford(mx));
    }
}

// ---------------- kernel 8: normalize by global max -------------------------
__global__ void k_norm(float* __restrict__ out) {
    int idx = blockIdx.x * blockDim.x + threadIdx.x;
    if (idx < 64 * 64 * 3) out[idx] = out[idx] / fordinv(g_maxord);
}

// ---------------- launch -----------------------------------------------------
extern "C" void kernel_launch(void* const* d_in, const int* in_sizes, int n_in,
                              void* d_out, int out_size) {
    const float* img     = (const float*)d_in[0];
    const float* mem     = (const float*)d_in[1];
    const float* mem2    = (const float*)d_in[2];
    const int*   mapping = (const int*)d_in[3];
    float* out = (float*)d_out;

    cudaFuncSetAttribute(k_gemm, cudaFuncAttributeMaxDynamicSharedMemorySize, GEMM_SMEM);

    k_init<<<(3 * XPC + 255) / 256, 256>>>(img);
    k_buildA<<<(NPAD * (KD / 16) + 255) / 256, 256>>>();
    k_bconv<<<NM, 256>>>(mem);
    dim3 gg(NPAD / BM, NM / BN);
    k_gemm<<<gg, 256, GEMM_SMEM>>>();
    k_rescore<<<NP, 256>>>(mem);
    k_recon<<<NP, 256>>>(mem2, mapping);
    k_overlap<<<192, 256>>>(out);
    k_norm<<<48, 256>>>(out);
}

// round 9
// speedup vs baseline: 1.1914x; 1.0164x over previous
#include <cuda_runtime.h>
#include <cuda_bf16.h>
#include <cstdint>

typedef unsigned long long ull;

#define NP 2809          // 53*53 patches
#define NPAD 2816        // 22*128
#define LW 53
#define NM 8192          // memories
#define KD 3072          // 3*32*32
#define XPW 84
#define XPC 7056         // 84*84
#define MARGIN 48.0f

#define BM 128
#define BN 128
#define BK 64              // fp8 elements per K-chunk (64 bytes/row)
#define NLOOP 24           // 2 chunks per loop
#define LDTB 80            // smem row stride in BYTES (64 + 16 pad, conflict-free)
#define STAGE_BYTES ((BM + BN) * LDTB)      // 20480
#define NSTAGE 4
#define GEMM_SMEM (NSTAGE * STAGE_BYTES)    // 81920

// ---------------- scratch (device globals; no allocations allowed) ----------
__device__ __align__(16) float g_xp[3 * XPC];
__device__ float g_memsq[NM];
__device__ ull   g_best[NP];                    // approx (pass1) key
__device__ ull   g_bestx[NP];                   // exact (rescore) key
__device__ __align__(16) float g_D[(size_t)NP * NM];       // ~92 MB approx distances
__device__ __align__(16) float g_recon[(size_t)NP * KD];   // ~34.5 MB
__device__ __align__(16) uint8_t g_A8[(size_t)NPAD * KD];  // 8.7 MB  e4m3 patches
__device__ __align__(16) uint8_t g_B8[(size_t)NM * KD];    // 25 MB   e4m3 memories
__device__ unsigned int g_maxord;

// ---------------- helpers ---------------------------------------------------
__device__ __forceinline__ unsigned int ford(float f) {
    unsigned int u = __float_as_uint(f);
    return (u & 0x80000000u) ? ~u : (u | 0x80000000u);
}
__device__ __forceinline__ float fordinv(unsigned int o) {
    unsigned int u = (o & 0x80000000u) ? (o ^ 0x80000000u) : ~o;
    return __uint_as_float(u);
}
__device__ __forceinline__ ull mkkey(float d, int m) {
    return ((ull)ford(d) << 32) | (unsigned int)m;
}
__device__ __forceinline__ uint32_t s2u(const void* p) {
    uint32_t a;
    asm("{ .reg .u64 t; cvta.to.shared.u64 t, %1; cvt.u32.u64 %0, t; }" : "=r"(a) : "l"(p));
    return a;
}
__device__ __forceinline__ uint32_t pack4_e4m3(float x0, float x1, float x2, float x3) {
    unsigned short lo, hi;
    asm("cvt.rn.satfinite.e4m3x2.f32 %0, %1, %2;" : "=h"(lo) : "f"(x1), "f"(x0));
    asm("cvt.rn.satfinite.e4m3x2.f32 %0, %1, %2;" : "=h"(hi) : "f"(x3), "f"(x2));
    return ((uint32_t)hi << 16) | (uint32_t)lo;
}
__device__ __forceinline__ void ldsm4(uint32_t* r, uint32_t addr) {
    asm volatile("ldmatrix.sync.aligned.m8n8.x4.shared.b16 {%0,%1,%2,%3}, [%4];"
                 : "=r"(r[0]), "=r"(r[1]), "=r"(r[2]), "=r"(r[3]) : "r"(addr));
}
__device__ __forceinline__ void mma16832(float* d, const uint32_t* a, const uint32_t* b) {
    asm volatile("mma.sync.aligned.m16n8k32.row.col.f32.e4m3.e4m3.f32 "
                 "{%0,%1,%2,%3}, {%4,%5,%6,%7}, {%8,%9}, {%0,%1,%2,%3};"
                 : "+f"(d[0]), "+f"(d[1]), "+f"(d[2]), "+f"(d[3])
                 : "r"(a[0]), "r"(a[1]), "r"(a[2]), "r"(a[3]), "r"(b[0]), "r"(b[1]));
}
__device__ __forceinline__ void cpasync16(uint32_t dst, const void* src) {
    asm volatile("cp.async.cg.shared.global [%0], [%1], 16;" :: "r"(dst), "l"(src));
}

// ---------------- kernel 1: build padded image + init -----------------------
__global__ void k_init(const float* __restrict__ img) {
    int idx = blockIdx.x * blockDim.x + threadIdx.x;
    if (idx < 3 * XPC) {
        int c = idx / XPC, rem = idx - c * XPC;
        int r = rem / XPW, col = rem - r * XPW;
        int h = r - 10, w = col - 10;
        float v = 0.f;
        if ((unsigned)h < 64u && (unsigned)w < 64u) v = img[(h * 64 + w) * 3 + c];
        g_xp[idx] = v;
    }
    if (idx < NP) g_best[idx] = ~0ull;
    if (idx == 0) g_maxord = 0u;
}

// ---------------- kernel 2: build e4m3 A matrix (patches) -------------------
__global__ void k_buildA() {
    int e = blockIdx.x * blockDim.x + threadIdx.x;   // NPAD * (KD/16)
    if (e >= NPAD * (KD / 16)) return;
    int m = e / (KD / 16), r = e - m * (KD / 16);
    int k = r * 16;
    uint32_t w0 = 0, w1 = 0, w2 = 0, w3 = 0;
    if (m < NP) {
        int i = m / LW, j = m - i * LW;
        int c = k >> 10, rem = k & 1023, kh = rem >> 5, kw = rem & 31;
        const float* src = &g_xp[c * XPC + (i + kh) * XPW + j + kw];
        w0 = pack4_e4m3(src[0],  src[1],  src[2],  src[3]);
        w1 = pack4_e4m3(src[4],  src[5],  src[6],  src[7]);
        w2 = pack4_e4m3(src[8],  src[9],  src[10], src[11]);
        w3 = pack4_e4m3(src[12], src[13], src[14], src[15]);
    }
    *(uint4*)&g_A8[(size_t)m * KD + k] = make_uint4(w0, w1, w2, w3);
}

// ---------------- kernel 3: convert mem to e4m3 + fused row squared norms ---
__global__ void __launch_bounds__(256) k_bconv(const float* __restrict__ mem) {
    __shared__ float red[8];
    int row = blockIdx.x, tid = threadIdx.x;
    const float4* src = (const float4*)(mem + (size_t)row * KD);
    float s = 0.f;
#pragma unroll
    for (int t = 0; t < 3; ++t) {                 // 3*256*4 = 3072
        int e = tid + t * 256;
        float4 v = src[e];
        *(uint32_t*)&g_B8[(size_t)row * KD + e * 4] = pack4_e4m3(v.x, v.y, v.z, v.w);
        s += v.x * v.x + v.y * v.y + v.z * v.z + v.w * v.w;
    }
#pragma unroll
    for (int o = 16; o; o >>= 1) s += __shfl_xor_sync(~0u, s, o);
    if ((tid & 31) == 0) red[tid >> 5] = s;
    __syncthreads();
    if (tid == 0) {
        float t = 0.f;
#pragma unroll
        for (int i = 0; i < 8; ++i) t += red[i];
        g_memsq[row] = t;
    }
}

// ---------------- kernel 4: e4m3 mma.sync GEMM + approx argmin + D write ----
// CTA 128x128, 2 K-chunks (128 fp8) per loop, 4-stage ring, ONE sync per loop.
// 2 CTAs/SM. 8 warps (2M x 4N), warp tile 64x32, hoisted global pointers.
__global__ void __launch_bounds__(256, 2) k_gemm() {
    extern __shared__ __align__(16) char dynsm[];
    __shared__ float s_msq[BN];

    int tid = threadIdx.x;
    int w = tid >> 5, lane = tid & 31;
    int warp_m = w & 1, warp_n = w >> 1;
    int p0 = blockIdx.x * BM, m0 = blockIdx.y * BN;

    if (tid < BN) s_msq[tid] = g_memsq[m0 + tid];

    uint32_t smbase = s2u(dynsm);

    // per-thread cp.async geometry: row = tid&127, 16B column cc0 = tid>>7
    int row = tid & 127, cc0 = tid >> 7;
    const uint8_t* gA = &g_A8[(size_t)(p0 + row) * KD + cc0 * 16];
    const uint8_t* gB = &g_B8[(size_t)(m0 + row) * KD + cc0 * 16];
    uint32_t dA0 = row * LDTB + cc0 * 16;
    uint32_t dB0 = BM * LDTB + row * LDTB + cc0 * 16;

    // load one loop's 2 chunks into stage pair {sp, sp+1}; gA/gB advanced by caller
    auto load_pair = [&](int sp) {
#pragma unroll
        for (int u = 0; u < 4; ++u) {             // u>>1 = chunk, u&1 = col half
            int koff = (u >> 1) * 64 + (u & 1) * 32;
            uint32_t sb = smbase + (sp + (u >> 1)) * STAGE_BYTES;
            cpasync16(sb + dA0 + (u & 1) * 32, gA + koff);
            cpasync16(sb + dB0 + (u & 1) * 32, gB + koff);
        }
        asm volatile("cp.async.commit_group;");
    };

    // ldmatrix byte offsets (16B segment = 16 fp8 k-values)
    uint32_t offA[4], offB[2];
#pragma unroll
    for (int fm = 0; fm < 4; ++fm)
        offA[fm] = (warp_m * 64 + fm * 16 + (lane & 15)) * LDTB + (lane >> 4) * 16;
#pragma unroll
    for (int fb = 0; fb < 2; ++fb)
        offB[fb] = BM * LDTB +
                   (warp_n * 32 + fb * 16 + (lane & 7) + ((lane >> 4) & 1) * 8) * LDTB +
                   ((lane >> 3) & 1) * 16;

    float acc[4][4][4];
#pragma unroll
    for (int fm = 0; fm < 4; ++fm)
#pragma unroll
        for (int fn = 0; fn < 4; ++fn)
#pragma unroll
            for (int q = 0; q < 4; ++q) acc[fm][fn][q] = 0.f;

    load_pair(0);                                  // loop 0 -> stages 0,1
    gA += 128; gB += 128;

    for (int L = 0; L < NLOOP; ++L) {
        asm volatile("cp.async.wait_group 0;");
        __syncthreads();
        if (L + 1 < NLOOP) {                       // prefetch loop L+1
            load_pair(((L + 1) & 1) * 2);
            gA += 128; gB += 128;
        }
        int sp = (L & 1) * 2;
#pragma unroll
        for (int ch = 0; ch < 2; ++ch) {
            uint32_t sb = smbase + (sp + ch) * STAGE_BYTES;
#pragma unroll
            for (int ks = 0; ks < 2; ++ks) {       // two k32 halves of 64B row
                uint32_t a[4][4], b[2][4];
#pragma unroll
                for (int fm = 0; fm < 4; ++fm) ldsm4(a[fm], sb + offA[fm] + ks * 32);
#pragma unroll
                for (int fb = 0; fb < 2; ++fb) ldsm4(b[fb], sb + offB[fb] + ks * 32);
#pragma unroll
                for (int fm = 0; fm < 4; ++fm)
#pragma unroll
                    for (int fb = 0; fb < 2; ++fb) {
                        mma16832(acc[fm][fb * 2],     a[fm], &b[fb][0]);
                        mma16832(acc[fm][fb * 2 + 1], a[fm], &b[fb][2]);
                    }
            }
        }
    }

    // register-direct epilogue: d = memsq - 2*score
    int q = lane & 3, rr = lane >> 2;
#pragma unroll
    for (int fm = 0; fm < 4; ++fm) {
        int pA = p0 + warp_m * 64 + fm * 16 + rr;
        int pB = pA + 8;
        bool vA = pA < NP, vB = pB < NP;
        ull keyA = ~0ull, keyB = ~0ull;
#pragma unroll
        for (int fn = 0; fn < 4; ++fn) {
            int nloc = warp_n * 32 + fn * 8 + q * 2;
            int mcol = m0 + nloc;
            float d0 = s_msq[nloc]     - 2.f * acc[fm][fn][0];
            float d1 = s_msq[nloc + 1] - 2.f * acc[fm][fn][1];
            float d2 = s_msq[nloc]     - 2.f * acc[fm][fn][2];
            float d3 = s_msq[nloc + 1] - 2.f * acc[fm][fn][3];
            keyA = min(keyA, min(mkkey(d0, mcol), mkkey(d1, mcol + 1)));
            keyB = min(keyB, min(mkkey(d2, mcol), mkkey(d3, mcol + 1)));
            if (vA) *(float2*)&g_D[(size_t)pA * NM + mcol] = make_float2(d0, d1);
            if (vB) *(float2*)&g_D[(size_t)pB * NM + mcol] = make_float2(d2, d3);
        }
#pragma unroll
        for (int o = 1; o < 4; o <<= 1) {
            keyA = min(keyA, __shfl_xor_sync(~0u, keyA, o));
            keyB = min(keyB, __shfl_xor_sync(~0u, keyB, o));
        }
        if (q == 0) {
            if (vA) atomicMin(&g_best[pA], keyA);
            if (vB) atomicMin(&g_best[pB], keyB);
        }
    }
}

// ---------------- kernel 5: exact rescore of margin candidates --------------
__global__ void k_rescore(const float* __restrict__ mem) {
    __shared__ __align__(16) float s_patch[KD];
    __shared__ int s_cand[128];
    __shared__ int s_n;
    __shared__ float s_part[8];
    __shared__ ull s_bestk;

    int p = blockIdx.x;
    int tid = threadIdx.x;
    int i = p / LW, j = p - i * LW;
    for (int k = tid; k < KD; k += 256) {
        int c = k >> 10, rem = k & 1023, kh = rem >> 5, kw = rem & 31;
        s_patch[k] = g_xp[c * XPC + (i + kh) * XPW + j + kw];
    }
    if (tid == 0) { s_n = 0; s_bestk = ~0ull; }
    __syncthreads();

    float thr = fordinv((unsigned int)(g_best[p] >> 32)) + MARGIN;
    const float* Drow = &g_D[(size_t)p * NM];
    for (int m = tid; m < NM; m += 256) {
        if (Drow[m] < thr) {
            int pos = atomicAdd(&s_n, 1);
            if (pos < 128) s_cand[pos] = m;
        }
    }
    __syncthreads();
    int n = min(s_n, 128);
    for (int ci = 0; ci < n; ++ci) {
        int m = s_cand[ci];
        const float* mr = mem + (size_t)m * KD;
        float part = 0.f;
        for (int k = tid; k < KD; k += 256) part += s_patch[k] * mr[k];
#pragma unroll
        for (int o = 16; o; o >>= 1) part += __shfl_xor_sync(~0u, part, o);
        if ((tid & 31) == 0) s_part[tid >> 5] = part;
        __syncthreads();
        if (tid == 0) {
            float dot = 0.f;
#pragma unroll
            for (int w = 0; w < 8; ++w) dot += s_part[w];
            float d = g_memsq[m] - 2.f * dot;
            ull k = mkkey(d, m);
            if (k < s_bestk) s_bestk = k;
        }
        __syncthreads();
    }
    if (tid == 0) g_bestx[p] = s_bestk;
}

// ---------------- kernel 6: gather recon rows -------------------------------
__global__ void k_recon(const float* __restrict__ mem2, const int* __restrict__ mapping) {
    int p = blockIdx.x;
    int nn = (int)(g_bestx[p] & 0xFFFFFFFFull);
    int row = mapping[nn];
    const float4* src = (const float4*)(mem2 + (size_t)row * KD);
    float4* dst = (float4*)(g_recon + (size_t)p * KD);
    for (int t = threadIdx.x; t < KD / 4; t += 256) dst[t] = src[t];
}

// ---------------- kernel 7: overlap-add (gather form) + block max -----------
__global__ void k_overlap(float* __restrict__ out) {
    __shared__ __align__(16) float s[LW * 32];
    __shared__ float red[4][64];
    int bc = blockIdx.x;
    int c = bc >> 6, h = bc & 63;
    int r = h + 10;
    int tid = threadIdx.x;
    int w = tid & 63, grp = tid >> 6;
    int cc = w + 10;
    int jmin = max(0, cc - 31), jmax = min(LW - 1, cc);
    int ilo = max(0, r - 31), ihi = min(LW - 1, r);

    float sum = 0.f;
    for (int i = ilo; i <= ihi; ++i) {
        int kh = r - i;
        __syncthreads();
        for (int e = tid; e < LW * 8; e += 256) {
            int jj = e >> 3, q = e & 7;
            *(float4*)&s[jj * 32 + q * 4] =
                *(const float4*)&g_recon[(size_t)(i * LW + jj) * KD + c * 1024 + kh * 32 + q * 4];
        }
        __syncthreads();
        for (int jx = jmin + grp; jx <= jmax; jx += 4)
            sum += s[jx * 32 + (cc - jx)];
    }
    red[grp][w] = sum;
    __syncthreads();
    if (tid < 64) {
        float v = red[0][tid] + red[1][tid] + red[2][tid] + red[3][tid];
        out[(h * 64 + tid) * 3 + c] = v;
        red[0][tid] = v;
    }
    __syncthreads();
    if (tid == 0) {
        float mx = red[0][0];
        for (int t = 1; t < 64; ++t) mx = fmaxf(mx, red[0][t]);
        atomicMax(&g_maxord, ford(mx));
    }
}

// ---------------- kernel 8: normalize by global max -------------------------
__global__ void k_norm(float* __restrict__ out) {
    int idx = blockIdx.x * blockDim.x + threadIdx.x;
    if (idx < 64 * 64 * 3) out[idx] = out[idx] / fordinv(g_maxord);
}

// ---------------- launch -----------------------------------------------------
extern "C" void kernel_launch(void* const* d_in, const int* in_sizes, int n_in,
                              void* d_out, int out_size) {
    const float* img     = (const float*)d_in[0];
    const float* mem     = (const float*)d_in[1];
    const float* mem2    = (const float*)d_in[2];
    const int*   mapping = (const int*)d_in[3];
    float* out = (float*)d_out;

    cudaFuncSetAttribute(k_gemm, cudaFuncAttributeMaxDynamicSharedMemorySize, GEMM_SMEM);

    k_init<<<(3 * XPC + 255) / 256, 256>>>(img);
    k_buildA<<<(NPAD * (KD / 16) + 255) / 256, 256>>>();
    k_bconv<<<NM, 256>>>(mem);
    dim3 gg(NPAD / BM, NM / BN);
    k_gemm<<<gg, 256, GEMM_SMEM>>>();
    k_rescore<<<NP, 256>>>(mem);
    k_recon<<<NP, 256>>>(mem2, mapping);
    k_overlap<<<192, 256>>>(out);
    k_norm<<<48, 256>>>(out);
}